// round 11
// baseline (speedup 1.0000x reference)
#include <cuda_runtime.h>
#include <cuda_bf16.h>
#include <math.h>

#define BB 2
#define SS 2048
#define DD 1024
#define HH 16
#define DHD 64
#define NROWS (BB*SS)        // 4096
#define NBH (BB*HH)          // 32
#define ATTN_SCALE 0.125f
#define CSHIFT 8.0f          // constant softmax shift (shift-invariant)

// ---------------------------------------------------------------------------
// Device-global scratch: everything bf16 hi/lo planes except l.
// ---------------------------------------------------------------------------
__device__ __nv_bfloat16 g_Xh[3][NROWS*DD];   // split query/key/value
__device__ __nv_bfloat16 g_Xl[3][NROWS*DD];
__device__ __nv_bfloat16 g_Wh[4][DD*DD];      // split Wq/Wk/Wv/Wo
__device__ __nv_bfloat16 g_Wl[4][DD*DD];
__device__ __nv_bfloat16 g_Qh[NBH*SS*DHD];    // [B,H,S,dh] planes
__device__ __nv_bfloat16 g_Ql[NBH*SS*DHD];
__device__ __nv_bfloat16 g_Kh[NBH*SS*DHD];
__device__ __nv_bfloat16 g_Kl[NBH*SS*DHD];
__device__ __nv_bfloat16 g_Vh[NBH*SS*DHD];
__device__ __nv_bfloat16 g_Vl[NBH*SS*DHD];
__device__ __nv_bfloat16 g_Oh[NROWS*DD];      // concat-heads planes
__device__ __nv_bfloat16 g_Ol[NROWS*DD];
__device__ float g_l[NBH*SS];

// ===========================================================================
// helpers
// ===========================================================================
__device__ __forceinline__ unsigned s2u(const void* p) {
    unsigned a;
    asm("{ .reg .u64 t; cvta.to.shared.u64 t, %1; cvt.u32.u64 %0, t; }"
        : "=r"(a) : "l"(p));
    return a;
}
__device__ __forceinline__ void mma16816(float* c, const unsigned* a, const unsigned* b) {
    asm volatile(
        "mma.sync.aligned.m16n8k16.row.col.f32.bf16.bf16.f32 "
        "{%0,%1,%2,%3}, {%4,%5,%6,%7}, {%8,%9}, {%0,%1,%2,%3};"
        : "+f"(c[0]), "+f"(c[1]), "+f"(c[2]), "+f"(c[3])
        : "r"(a[0]), "r"(a[1]), "r"(a[2]), "r"(a[3]), "r"(b[0]), "r"(b[1]));
}
__device__ __forceinline__ void ldm_x4(unsigned* r, unsigned addr) {
    asm volatile("ldmatrix.sync.aligned.m8n8.x4.shared.b16 {%0,%1,%2,%3}, [%4];"
        : "=r"(r[0]), "=r"(r[1]), "=r"(r[2]), "=r"(r[3]) : "r"(addr));
}
__device__ __forceinline__ void ldm_x4_t(unsigned* r, unsigned addr) {
    asm volatile("ldmatrix.sync.aligned.m8n8.x4.trans.shared.b16 {%0,%1,%2,%3}, [%4];"
        : "=r"(r[0]), "=r"(r[1]), "=r"(r[2]), "=r"(r[3]) : "r"(addr));
}
__device__ __forceinline__ void split2(float x, __nv_bfloat16& h, __nv_bfloat16& l) {
    h = __float2bfloat16_rn(x);
    l = __float2bfloat16_rn(x - __bfloat162float(h));
}
__device__ __forceinline__ unsigned pk(__nv_bfloat16 a, __nv_bfloat16 b) {
    __nv_bfloat162 t(a, b);
    return *(unsigned*)&t;
}
__device__ __forceinline__ void cpa16(unsigned dst, const void* src) {
    asm volatile("cp.async.cg.shared.global [%0], [%1], 16;" :: "r"(dst), "l"(src));
}
#define CP_COMMIT() asm volatile("cp.async.commit_group;" ::: "memory")
#define CP_WAIT0()  asm volatile("cp.async.wait_group 0;" ::: "memory")
#define CP_WAIT1()  asm volatile("cp.async.wait_group 1;" ::: "memory")

// ---------------------------------------------------------------------------
// Prep: split inputs (q/k/v) and weights into bf16 hi/lo planes once.
// ---------------------------------------------------------------------------
__global__ __launch_bounds__(256) void prep_split(
    const float* __restrict__ q, const float* __restrict__ k,
    const float* __restrict__ v,
    const float* __restrict__ w0, const float* __restrict__ w1,
    const float* __restrict__ w2, const float* __restrict__ w3)
{
    const int z = blockIdx.y;
    const float* src;
    __nv_bfloat16 *dh, *dl;
    int n4;
    if (z < 3) {
        src = (z == 0) ? q : (z == 1) ? k : v;
        dh = g_Xh[z]; dl = g_Xl[z]; n4 = NROWS*DD/4;
    } else {
        int w = z - 3;
        src = (w == 0) ? w0 : (w == 1) ? w1 : (w == 2) ? w2 : w3;
        dh = g_Wh[w]; dl = g_Wl[w]; n4 = DD*DD/4;
    }
    for (int i = blockIdx.x * 256 + threadIdx.x; i < n4; i += gridDim.x * 256) {
        float4 x = ((const float4*)src)[i];
        __nv_bfloat16 h[4], l[4];
        split2(x.x, h[0], l[0]); split2(x.y, h[1], l[1]);
        split2(x.z, h[2], l[2]); split2(x.w, h[3], l[3]);
        ((uint2*)dh)[i] = make_uint2(pk(h[0], h[1]), pk(h[2], h[3]));
        ((uint2*)dl)[i] = make_uint2(pk(l[0], l[1]), pk(l[2], l[3]));
    }
}

// ---------------------------------------------------------------------------
// Projection GEMM (HMMA, bf16 planes, cp.async double-buffered).
// mode = mode_base + blockIdx.z. 0/1/2 -> Q/K/V planes; 3 -> fp32 out.
// ---------------------------------------------------------------------------
#define PROWB 80
#define PPLANE 10240
#define PSTAGE (4*PPLANE)
#define PROJ_SMEM (2*PSTAGE)               // 81920

__global__ __launch_bounds__(256) void proj_gemm_bf(
    const float* __restrict__ b0p, const float* __restrict__ b1p,
    const float* __restrict__ b2p, float* __restrict__ out_ext, int mode_base)
{
    extern __shared__ char smem[];
    const unsigned sb = s2u(smem);
    const int mode = mode_base + blockIdx.z;
    const int tid = threadIdx.x, wid = tid >> 5, lane = tid & 31;
    const int wm = wid >> 1, wn = wid & 1;
    const int rowBase = blockIdx.y * 128;
    const int colBase = blockIdx.x * 128;

    const float* bias = (blockIdx.z == 0) ? b0p : (blockIdx.z == 1) ? b1p : b2p;
    const __nv_bfloat16* Xh = (mode == 3) ? g_Oh : g_Xh[mode];
    const __nv_bfloat16* Xl = (mode == 3) ? g_Ol : g_Xl[mode];
    const __nv_bfloat16* Wh = g_Wh[mode];
    const __nv_bfloat16* Wl = g_Wl[mode];

    float acc[2][8][4];
#pragma unroll
    for (int i = 0; i < 2; i++)
#pragma unroll
        for (int j = 0; j < 8; j++)
#pragma unroll
            for (int v = 0; v < 4; v++) acc[i][j][v] = 0.f;

    auto ISSUE = [&](int c) {
        const int k0 = c * 32;
        const unsigned st = sb + (unsigned)(c & 1) * PSTAGE;
        for (int i = tid; i < 2048; i += 256) {
            int pl = i >> 9, r = (i >> 2) & 127, sg = i & 3;
            const __nv_bfloat16* srcp;
            if (pl == 0)      srcp = Xh + (size_t)(rowBase + r) * DD + k0 + sg*8;
            else if (pl == 1) srcp = Xl + (size_t)(rowBase + r) * DD + k0 + sg*8;
            else if (pl == 2) srcp = Wh + (size_t)(colBase + r) * DD + k0 + sg*8;
            else              srcp = Wl + (size_t)(colBase + r) * DD + k0 + sg*8;
            cpa16(st + (unsigned)pl * PPLANE + (unsigned)r * PROWB + sg*16, srcp);
        }
    };

    ISSUE(0); CP_COMMIT();

    const int a_row = wm*32 + (lane & 15);
    const int a_c8  = (lane >> 4) << 3;
    const int b_row = wn*64 + (((lane >> 4) & 1) << 3) + (lane & 7);
    const int b_c8  = ((lane >> 3) & 1) << 3;

    for (int c = 0; c < 32; c++) {
        if (c < 31) { ISSUE(c + 1); CP_COMMIT(); CP_WAIT1(); }
        else        { CP_WAIT0(); }
        __syncthreads();

        const unsigned sA  = sb + (unsigned)(c & 1) * PSTAGE;
        const unsigned sAl = sA + PPLANE;
        const unsigned sBh = sA + 2*PPLANE;
        const unsigned sBl = sA + 3*PPLANE;

#pragma unroll
        for (int ks = 0; ks < 2; ks++) {
            unsigned ahi[8], alo[8];
#pragma unroll
            for (int t = 0; t < 2; t++) {
                unsigned ar = (unsigned)(a_row + t*16) * PROWB
                            + (unsigned)(ks*16 + a_c8) * 2;
                ldm_x4(ahi + t*4, sA  + ar);
                ldm_x4(alo + t*4, sAl + ar);
            }
#pragma unroll
            for (int jp = 0; jp < 4; jp++) {
                unsigned br = (unsigned)(b_row + jp*16) * PROWB
                            + (unsigned)(ks*16 + b_c8) * 2;
                unsigned bhi[4], blo[4];
                ldm_x4(bhi, sBh + br);
                ldm_x4(blo, sBl + br);
#pragma unroll
                for (int tn = 0; tn < 2; tn++) {
#pragma unroll
                    for (int mi = 0; mi < 2; mi++) {
                        float* a4 = acc[mi][jp*2 + tn];
                        mma16816(a4, ahi + mi*4, bhi + tn*2);
                        mma16816(a4, ahi + mi*4, blo + tn*2);
                        mma16816(a4, alo + mi*4, bhi + tn*2);
                    }
                }
            }
        }
        __syncthreads();
    }

    const int g = lane >> 2, tig = lane & 3;
    __nv_bfloat16* Dh = (mode == 0) ? g_Qh : (mode == 1) ? g_Kh : g_Vh;
    __nv_bfloat16* Dl = (mode == 0) ? g_Ql : (mode == 1) ? g_Kl : g_Vl;
#pragma unroll
    for (int mi = 0; mi < 2; mi++) {
#pragma unroll
        for (int nj = 0; nj < 8; nj++) {
            int col = colBase + wn*64 + nj*8 + tig*2;
            float b0 = __ldg(&bias[col]);
            float b1 = __ldg(&bias[col+1]);
#pragma unroll
            for (int rh = 0; rh < 2; rh++) {
                int row = rowBase + wm*32 + mi*16 + g + rh*8;
                float v0 = acc[mi][nj][rh*2+0] + b0;
                float v1 = acc[mi][nj][rh*2+1] + b1;
                if (mode < 3) {
                    int b_ = row >> 11, s_ = row & (SS - 1);
                    int h_ = col >> 6,  d_ = col & 63;
                    size_t idx = (size_t)(((b_*HH) + h_)*SS + s_)*DHD + d_;
                    __nv_bfloat16 h0, l0, h1, l1;
                    split2(v0, h0, l0); split2(v1, h1, l1);
                    *(unsigned*)(Dh + idx) = pk(h0, h1);
                    *(unsigned*)(Dl + idx) = pk(l0, l1);
                } else {
                    float2 w2 = make_float2(v0, v1);
                    *(float2*)(out_ext + (size_t)row * DD + col) = w2;
                }
            }
        }
    }
}

// ---------------------------------------------------------------------------
// Pass 1 (HMMA): S = Q K^T * scale; t = exp(s - 8) -> attn; l = row sums.
// ---------------------------------------------------------------------------
#define KSTR 144
#define KPLANE (128*KSTR)                  // 18432
#define SK_OFF (2*KPLANE)
#define SRED (SK_OFF + 2*2*KPLANE)         // 110592
#define S1_SMEM (SRED + 128*2*4)           // 111616

__global__ __launch_bounds__(256) void scores_hmma(float* __restrict__ attn)
{
    extern __shared__ char sm[];
    const unsigned sb = s2u(sm);
    const int qt = (SS/128 - 1) - blockIdx.x;   // heavy CTAs first
    const int h = blockIdx.y, b = blockIdx.z;
    const int bh = b*HH + h;
    const int tid = threadIdx.x, wid = tid>>5, lane = tid&31;
    const int wm = wid>>1, wn = wid&1;
    const int g = lane>>2, tig = lane&3;
    const int qtb = qt*128;

    float* attn_bh = attn + (size_t)bh*SS*SS;
    float* redl = (float*)(sm + SRED);

    for (int i = tid; i < 2048; i += 256) {
        int pl = i >> 10, r = (i >> 3) & 127, sg = i & 7;
        const __nv_bfloat16* src =
            (pl ? g_Ql : g_Qh) + (size_t)(bh*SS + qtb + r)*DHD + sg*8;
        cpa16(sb + (unsigned)pl*KPLANE + (unsigned)r*KSTR + sg*16, src);
    }
    auto ISSUEK = [&](int kt) {
        const unsigned st = sb + SK_OFF + (unsigned)(kt & 1) * (2*KPLANE);
        const int ktb = kt*128;
        for (int i = tid; i < 2048; i += 256) {
            int pl = i >> 10, r = (i >> 3) & 127, sg = i & 7;
            const __nv_bfloat16* src =
                (pl ? g_Kl : g_Kh) + (size_t)(bh*SS + ktb + r)*DHD + sg*8;
            cpa16(st + (unsigned)pl*KPLANE + (unsigned)r*KSTR + sg*16, src);
        }
    };
    ISSUEK(0); CP_COMMIT();

    float rsum[4] = {0.f, 0.f, 0.f, 0.f};

    const int a_row = wm*32 + (lane&15);
    const int a_c8  = (lane>>4) << 3;
    const int b_row = wn*64 + (((lane>>4)&1)<<3) + (lane&7);
    const int b_c8  = ((lane>>3)&1) << 3;

    for (int kt = 0; kt <= qt; kt++) {
        if (kt < qt) { ISSUEK(kt + 1); CP_COMMIT(); CP_WAIT1(); }
        else         { CP_WAIT0(); }
        __syncthreads();

        const unsigned sKh = sb + SK_OFF + (unsigned)(kt & 1) * (2*KPLANE);
        const unsigned sKl = sKh + KPLANE;
        const int ktb = kt*128;

        float acc[2][8][4];
#pragma unroll
        for (int i = 0; i < 2; i++)
#pragma unroll
            for (int j = 0; j < 8; j++)
#pragma unroll
                for (int v = 0; v < 4; v++) acc[i][j][v] = 0.f;

#pragma unroll
        for (int ks = 0; ks < 4; ks++) {
            unsigned arow = (unsigned)a_row * KSTR + (unsigned)(ks*16 + a_c8)*2;
            unsigned ahi[2][4], alo[2][4];
            ldm_x4(ahi[0], sb + arow);
            ldm_x4(alo[0], sb + KPLANE + arow);
            ldm_x4(ahi[1], sb + arow + 16*KSTR);
            ldm_x4(alo[1], sb + KPLANE + arow + 16*KSTR);
#pragma unroll
            for (int jp = 0; jp < 4; jp++) {
                unsigned br = (unsigned)(b_row + jp*16)*KSTR
                            + (unsigned)(ks*16 + b_c8)*2;
                unsigned bhi[4], blo[4];
                ldm_x4(bhi, sKh + br);
                ldm_x4(blo, sKl + br);
#pragma unroll
                for (int tn = 0; tn < 2; tn++) {
#pragma unroll
                    for (int mi = 0; mi < 2; mi++) {
                        float* a4 = acc[mi][jp*2+tn];
                        mma16816(a4, ahi[mi], bhi + tn*2);
                        mma16816(a4, ahi[mi], blo + tn*2);
                        mma16816(a4, alo[mi], bhi + tn*2);
                    }
                }
            }
        }

        const bool diag = (kt == qt);
#pragma unroll
        for (int mi = 0; mi < 2; mi++) {
#pragma unroll
            for (int rh = 0; rh < 2; rh++) {
                int qgl = wm*32 + mi*16 + g + rh*8;
#pragma unroll
                for (int nj = 0; nj < 8; nj++) {
                    int kgl = wn*64 + nj*8 + tig*2;
                    float t0 = __expf(fmaf(acc[mi][nj][rh*2+0], ATTN_SCALE, -CSHIFT));
                    float t1 = __expf(fmaf(acc[mi][nj][rh*2+1], ATTN_SCALE, -CSHIFT));
                    if (diag) {
                        if (kgl   > qgl) t0 = 0.f;
                        if (kgl+1 > qgl) t1 = 0.f;
                    }
                    rsum[mi*2+rh] += t0 + t1;
                    float2 w2 = make_float2(t0, t1);
                    *(float2*)(attn_bh + (size_t)(qtb+qgl)*SS + ktb + kgl) = w2;
                }
            }
        }
        __syncthreads();
    }

#pragma unroll
    for (int i = 0; i < 4; i++) {
        rsum[i] += __shfl_xor_sync(0xffffffff, rsum[i], 1);
        rsum[i] += __shfl_xor_sync(0xffffffff, rsum[i], 2);
    }
    if (tig == 0) {
#pragma unroll
        for (int i = 0; i < 4; i++) {
            int rl = wm*32 + (i>>1)*16 + g + (i&1)*8;
            redl[rl*2 + wn] = rsum[i];
        }
    }
    __syncthreads();
    if (tid < 128)
        g_l[(size_t)bh*SS + qtb + tid] = redl[tid*2] + redl[tid*2+1];
}

// ---------------------------------------------------------------------------
// Pass 2 (HMMA), pipelined: t staged via cp.async, normalize from SMEM,
// next tile's t+V reads overlap the current MMA. Zero-fill issued first.
// ---------------------------------------------------------------------------
#define PSTR2 272
#define PPL2 (128*PSTR2)                   // 34816
#define AV_TRAW (2*PPL2)                   // 69632, 65536 bytes (128 x 512B)
#define AV_V (AV_TRAW + 65536)             // 135168: 2 stages x (Vh,Vl)
#define AV_LI (AV_V + 2*2*KPLANE)          // 208896
#define S2_SMEM (AV_LI + 128*4)            // 209408

__global__ __launch_bounds__(256) void av_hmma(float* __restrict__ attn)
{
    extern __shared__ char sm[];
    const unsigned sb = s2u(sm);
    const int qt = (SS/128 - 1) - blockIdx.x;
    const int h = blockIdx.y, b = blockIdx.z;
    const int bh = b*HH + h;
    const int tid = threadIdx.x, wid = tid>>5, lane = tid&31;
    const int wm = wid>>1, wn = wid&1;
    const int g = lane>>2, tig = lane&3;
    const int qtb = qt*128;

    float* attn_bh = attn + (size_t)bh*SS*SS;
    float* li = (float*)(sm + AV_LI);

    if (tid < 128) li[tid] = 1.f / g_l[(size_t)bh*SS + qtb + tid];

    // zero-fill upper triangle FIRST (fire-and-forget, drains during mainloop)
    {
        float4 z4 = make_float4(0.f, 0.f, 0.f, 0.f);
        for (int kt = qt + 1; kt < SS/128; kt++) {
            for (int v = tid; v < 4096; v += 256) {
                int r = v>>5, c4 = (v&31)<<2;
                *(float4*)(attn_bh + (size_t)(qtb + r)*SS + kt*128 + c4) = z4;
            }
        }
    }

    // stage a full 128x128 fp32 t tile: 4096 x 16B cp.async
    auto ISSUE_T = [&](int kt) {
        const int ktb = kt*128;
        for (int i = tid; i < 4096; i += 256) {
            int r = i >> 5, sg = i & 31;       // 32 x 16B per 128-float row
            cpa16(sb + AV_TRAW + (unsigned)r*512 + sg*16,
                  attn_bh + (size_t)(qtb + r)*SS + ktb + sg*4);
        }
    };
    auto ISSUE_V = [&](int kt) {
        const unsigned st = sb + AV_V + (unsigned)(kt & 1) * (2*KPLANE);
        const int ktb = kt*128;
        for (int i = tid; i < 2048; i += 256) {
            int pl = i >> 10, r = (i >> 3) & 127, sg = i & 7;
            const __nv_bfloat16* src =
                (pl ? g_Vl : g_Vh) + (size_t)(bh*SS + ktb + r)*DHD + sg*8;
            cpa16(st + (unsigned)pl*KPLANE + (unsigned)r*KSTR + sg*16, src);
        }
    };

    ISSUE_T(0); ISSUE_V(0); CP_COMMIT();

    float acc[2][4][4];
#pragma unroll
    for (int i = 0; i < 2; i++)
#pragma unroll
        for (int j = 0; j < 4; j++)
#pragma unroll
            for (int v = 0; v < 4; v++) acc[i][j][v] = 0.f;

    for (int kt = 0; kt <= qt; kt++) {
        const int ktb = kt*128;
        CP_WAIT0();
        __syncthreads();                       // traw(kt), V(kt), li ready

        // convert: traw -> p (STG) + P planes (STS)
        for (int v = tid; v < 4096; v += 256) {
            int r = v>>5, c4 = (v&31)<<2;
            float4 t4 = *(const float4*)(sm + AV_TRAW + r*512 + c4*4);
            float s = li[r];
            t4.x *= s; t4.y *= s; t4.z *= s; t4.w *= s;
            *(float4*)(attn_bh + (size_t)(qtb + r)*SS + ktb + c4) = t4;
            __nv_bfloat16 hh[4], ll[4];
            split2(t4.x,hh[0],ll[0]); split2(t4.y,hh[1],ll[1]);
            split2(t4.z,hh[2],ll[2]); split2(t4.w,hh[3],ll[3]);
            unsigned so = (unsigned)r*PSTR2 + (unsigned)c4*2;
            *(uint2*)(sm + so)        = make_uint2(pk(hh[0],hh[1]), pk(hh[2],hh[3]));
            *(uint2*)(sm + PPL2 + so) = make_uint2(pk(ll[0],ll[1]), pk(ll[2],ll[3]));
        }
        __syncthreads();                       // planes visible; traw consumed

        if (kt < qt) { ISSUE_T(kt + 1); ISSUE_V(kt + 1); CP_COMMIT(); }

        // O += P(128x128) @ V(128x64)   (overlaps with next tile's loads)
        const unsigned sVh = sb + AV_V + (unsigned)(kt & 1) * (2*KPLANE);
        const unsigned sVl = sVh + KPLANE;
#pragma unroll
        for (int ks = 0; ks < 8; ks++) {
            unsigned arow = (unsigned)(wm*32 + (lane&15))*PSTR2
                          + (unsigned)(ks*16 + ((lane>>4)<<3))*2;
            unsigned ahi[2][4], alo[2][4];
            ldm_x4(ahi[0], sb + arow);
            ldm_x4(alo[0], sb + PPL2 + arow);
            ldm_x4(ahi[1], sb + arow + 16*PSTR2);
            ldm_x4(alo[1], sb + PPL2 + arow + 16*PSTR2);
#pragma unroll
            for (int jp = 0; jp < 2; jp++) {
                unsigned brow = (unsigned)(ks*16 + (((lane>>3)&1)<<3) + (lane&7))*KSTR
                              + (unsigned)(wn*32 + jp*16 + (((lane>>4)&1)<<3))*2;
                unsigned bhi[4], blo[4];
                ldm_x4_t(bhi, sVh + brow);
                ldm_x4_t(blo, sVl + brow);
#pragma unroll
                for (int tn = 0; tn < 2; tn++) {
#pragma unroll
                    for (int mi = 0; mi < 2; mi++) {
                        float* a4 = acc[mi][jp*2+tn];
                        mma16816(a4, ahi[mi], bhi + tn*2);
                        mma16816(a4, ahi[mi], blo + tn*2);
                        mma16816(a4, alo[mi], bhi + tn*2);
                    }
                }
            }
        }
    }

    // write O planes (bf16 hi/lo) for the output projection
#pragma unroll
    for (int mi = 0; mi < 2; mi++) {
#pragma unroll
        for (int rh = 0; rh < 2; rh++) {
            int qg = qtb + wm*32 + mi*16 + g + rh*8;
            int n = b*SS + qg;
#pragma unroll
            for (int nj = 0; nj < 4; nj++) {
                int dd = h*DHD + wn*32 + nj*8 + tig*2;
                __nv_bfloat16 h0, l0, h1, l1;
                split2(acc[mi][nj][rh*2+0], h0, l0);
                split2(acc[mi][nj][rh*2+1], h1, l1);
                size_t idx = (size_t)n * DD + dd;
                *(unsigned*)(g_Oh + idx) = pk(h0, h1);
                *(unsigned*)(g_Ol + idx) = pk(l0, l1);
            }
        }
    }
}

// ---------------------------------------------------------------------------
extern "C" void kernel_launch(void* const* d_in, const int* in_sizes, int n_in,
                              void* d_out, int out_size)
{
    const float* qkv[3] = {nullptr, nullptr, nullptr};
    const float* Wm[4]  = {nullptr, nullptr, nullptr, nullptr};
    const float* bm[4]  = {nullptr, nullptr, nullptr, nullptr};
    int nq = 0, nw = 0, nb = 0;
    for (int i = 0; i < n_in; i++) {
        int sz = in_sizes[i];
        if (sz == NROWS*DD)      { if (nq < 3) qkv[nq++] = (const float*)d_in[i]; }
        else if (sz == DD*DD)    { if (nw < 4) Wm[nw++]  = (const float*)d_in[i]; }
        else if (sz == DD)       { if (nb < 4) bm[nb++]  = (const float*)d_in[i]; }
    }

    float* out  = (float*)d_out;
    float* attn = out + (size_t)NROWS * DD;

    static int smem_set = 0;
    if (!smem_set) {
        cudaFuncSetAttribute(proj_gemm_bf,
                             cudaFuncAttributeMaxDynamicSharedMemorySize, PROJ_SMEM);
        cudaFuncSetAttribute(scores_hmma,
                             cudaFuncAttributeMaxDynamicSharedMemorySize, S1_SMEM);
        cudaFuncSetAttribute(av_hmma,
                             cudaFuncAttributeMaxDynamicSharedMemorySize, S2_SMEM);
        smem_set = 1;
    }

    dim3 blk(256);
    prep_split<<<dim3(1024, 7), blk>>>(qkv[0], qkv[1], qkv[2],
                                       Wm[0], Wm[1], Wm[2], Wm[3]);

    // fused QKV projections (grid.z = 3)
    proj_gemm_bf<<<dim3(DD/128, NROWS/128, 3), blk, PROJ_SMEM>>>(
        bm[0], bm[1], bm[2], nullptr, 0);

    dim3 agrid(SS/128, HH, BB);               // (16, 16, 2)
    scores_hmma<<<agrid, blk, S1_SMEM>>>(attn);
    av_hmma<<<agrid, blk, S2_SMEM>>>(attn);

    // output projection (mode 3)
    proj_gemm_bf<<<dim3(DD/128, NROWS/128, 1), blk, PROJ_SMEM>>>(
        bm[3], nullptr, nullptr, out, 3);

    (void)out_size;
}

// round 12
// speedup vs baseline: 1.3665x; 1.3665x over previous
#include <cuda_runtime.h>
#include <cuda_bf16.h>
#include <math.h>

#define BB 2
#define SS 2048
#define DD 1024
#define HH 16
#define DHD 64
#define NROWS (BB*SS)        // 4096
#define NBH (BB*HH)          // 32
#define ATTN_SCALE 0.125f
#define CSHIFT 8.0f          // constant softmax shift (shift-invariant)

// ---------------------------------------------------------------------------
// Device-global scratch: everything bf16 hi/lo planes except l.
// ---------------------------------------------------------------------------
__device__ __nv_bfloat16 g_Xh[3][NROWS*DD];   // split query/key/value
__device__ __nv_bfloat16 g_Xl[3][NROWS*DD];
__device__ __nv_bfloat16 g_Wh[4][DD*DD];      // split Wq/Wk/Wv/Wo
__device__ __nv_bfloat16 g_Wl[4][DD*DD];
__device__ __nv_bfloat16 g_Qh[NBH*SS*DHD];    // [B,H,S,dh] planes
__device__ __nv_bfloat16 g_Ql[NBH*SS*DHD];
__device__ __nv_bfloat16 g_Kh[NBH*SS*DHD];
__device__ __nv_bfloat16 g_Kl[NBH*SS*DHD];
__device__ __nv_bfloat16 g_Vh[NBH*SS*DHD];
__device__ __nv_bfloat16 g_Vl[NBH*SS*DHD];
__device__ __nv_bfloat16 g_Oh[NROWS*DD];      // concat-heads planes
__device__ __nv_bfloat16 g_Ol[NROWS*DD];
__device__ float g_l[NBH*SS];

// ===========================================================================
// helpers
// ===========================================================================
__device__ __forceinline__ unsigned s2u(const void* p) {
    unsigned a;
    asm("{ .reg .u64 t; cvta.to.shared.u64 t, %1; cvt.u32.u64 %0, t; }"
        : "=r"(a) : "l"(p));
    return a;
}
__device__ __forceinline__ void mma16816(float* c, const unsigned* a, const unsigned* b) {
    asm volatile(
        "mma.sync.aligned.m16n8k16.row.col.f32.bf16.bf16.f32 "
        "{%0,%1,%2,%3}, {%4,%5,%6,%7}, {%8,%9}, {%0,%1,%2,%3};"
        : "+f"(c[0]), "+f"(c[1]), "+f"(c[2]), "+f"(c[3])
        : "r"(a[0]), "r"(a[1]), "r"(a[2]), "r"(a[3]), "r"(b[0]), "r"(b[1]));
}
__device__ __forceinline__ void ldm_x4(unsigned* r, unsigned addr) {
    asm volatile("ldmatrix.sync.aligned.m8n8.x4.shared.b16 {%0,%1,%2,%3}, [%4];"
        : "=r"(r[0]), "=r"(r[1]), "=r"(r[2]), "=r"(r[3]) : "r"(addr));
}
__device__ __forceinline__ void ldm_x4_t(unsigned* r, unsigned addr) {
    asm volatile("ldmatrix.sync.aligned.m8n8.x4.trans.shared.b16 {%0,%1,%2,%3}, [%4];"
        : "=r"(r[0]), "=r"(r[1]), "=r"(r[2]), "=r"(r[3]) : "r"(addr));
}
__device__ __forceinline__ void split2(float x, __nv_bfloat16& h, __nv_bfloat16& l) {
    h = __float2bfloat16_rn(x);
    l = __float2bfloat16_rn(x - __bfloat162float(h));
}
__device__ __forceinline__ unsigned pk(__nv_bfloat16 a, __nv_bfloat16 b) {
    __nv_bfloat162 t(a, b);
    return *(unsigned*)&t;
}
__device__ __forceinline__ void cpa16(unsigned dst, const void* src) {
    asm volatile("cp.async.cg.shared.global [%0], [%1], 16;" :: "r"(dst), "l"(src));
}
#define CP_COMMIT() asm volatile("cp.async.commit_group;" ::: "memory")
#define CP_WAIT0()  asm volatile("cp.async.wait_group 0;" ::: "memory")
#define CP_WAIT1()  asm volatile("cp.async.wait_group 1;" ::: "memory")

// ---------------------------------------------------------------------------
// Prep: split inputs (q/k/v) and weights into bf16 hi/lo planes once.
// ---------------------------------------------------------------------------
__global__ __launch_bounds__(256) void prep_split(
    const float* __restrict__ q, const float* __restrict__ k,
    const float* __restrict__ v,
    const float* __restrict__ w0, const float* __restrict__ w1,
    const float* __restrict__ w2, const float* __restrict__ w3)
{
    const int z = blockIdx.y;
    const float* src;
    __nv_bfloat16 *dh, *dl;
    int n4;
    if (z < 3) {
        src = (z == 0) ? q : (z == 1) ? k : v;
        dh = g_Xh[z]; dl = g_Xl[z]; n4 = NROWS*DD/4;
    } else {
        int w = z - 3;
        src = (w == 0) ? w0 : (w == 1) ? w1 : (w == 2) ? w2 : w3;
        dh = g_Wh[w]; dl = g_Wl[w]; n4 = DD*DD/4;
    }
    for (int i = blockIdx.x * 256 + threadIdx.x; i < n4; i += gridDim.x * 256) {
        float4 x = ((const float4*)src)[i];
        __nv_bfloat16 h[4], l[4];
        split2(x.x, h[0], l[0]); split2(x.y, h[1], l[1]);
        split2(x.z, h[2], l[2]); split2(x.w, h[3], l[3]);
        ((uint2*)dh)[i] = make_uint2(pk(h[0], h[1]), pk(h[2], h[3]));
        ((uint2*)dl)[i] = make_uint2(pk(l[0], l[1]), pk(l[2], l[3]));
    }
}

// ---------------------------------------------------------------------------
// Projection GEMM (HMMA, bf16 planes, cp.async double-buffered).
// Sequential launches (one mode each) keep the ~41 MB working set L2-resident.
// mode 0/1/2 -> Q/K/V planes; 3 -> fp32 out.
// ---------------------------------------------------------------------------
#define PROWB 80
#define PPLANE 10240
#define PSTAGE (4*PPLANE)
#define PROJ_SMEM (2*PSTAGE)               // 81920

__global__ __launch_bounds__(256) void proj_gemm_bf(
    const float* __restrict__ bias, float* __restrict__ out_ext, int mode)
{
    extern __shared__ char smem[];
    const unsigned sb = s2u(smem);
    const int tid = threadIdx.x, wid = tid >> 5, lane = tid & 31;
    const int wm = wid >> 1, wn = wid & 1;
    const int rowBase = blockIdx.y * 128;
    const int colBase = blockIdx.x * 128;

    const __nv_bfloat16* Xh = (mode == 3) ? g_Oh : g_Xh[mode];
    const __nv_bfloat16* Xl = (mode == 3) ? g_Ol : g_Xl[mode];
    const __nv_bfloat16* Wh = g_Wh[mode];
    const __nv_bfloat16* Wl = g_Wl[mode];

    float acc[2][8][4];
#pragma unroll
    for (int i = 0; i < 2; i++)
#pragma unroll
        for (int j = 0; j < 8; j++)
#pragma unroll
            for (int v = 0; v < 4; v++) acc[i][j][v] = 0.f;

    auto ISSUE = [&](int c) {
        const int k0 = c * 32;
        const unsigned st = sb + (unsigned)(c & 1) * PSTAGE;
        for (int i = tid; i < 2048; i += 256) {
            int pl = i >> 9, r = (i >> 2) & 127, sg = i & 3;
            const __nv_bfloat16* srcp;
            if (pl == 0)      srcp = Xh + (size_t)(rowBase + r) * DD + k0 + sg*8;
            else if (pl == 1) srcp = Xl + (size_t)(rowBase + r) * DD + k0 + sg*8;
            else if (pl == 2) srcp = Wh + (size_t)(colBase + r) * DD + k0 + sg*8;
            else              srcp = Wl + (size_t)(colBase + r) * DD + k0 + sg*8;
            cpa16(st + (unsigned)pl * PPLANE + (unsigned)r * PROWB + sg*16, srcp);
        }
    };

    ISSUE(0); CP_COMMIT();

    const int a_row = wm*32 + (lane & 15);
    const int a_c8  = (lane >> 4) << 3;
    const int b_row = wn*64 + (((lane >> 4) & 1) << 3) + (lane & 7);
    const int b_c8  = ((lane >> 3) & 1) << 3;

    for (int c = 0; c < 32; c++) {
        if (c < 31) { ISSUE(c + 1); CP_COMMIT(); CP_WAIT1(); }
        else        { CP_WAIT0(); }
        __syncthreads();

        const unsigned sA  = sb + (unsigned)(c & 1) * PSTAGE;
        const unsigned sAl = sA + PPLANE;
        const unsigned sBh = sA + 2*PPLANE;
        const unsigned sBl = sA + 3*PPLANE;

#pragma unroll
        for (int ks = 0; ks < 2; ks++) {
            unsigned ahi[8], alo[8];
#pragma unroll
            for (int t = 0; t < 2; t++) {
                unsigned ar = (unsigned)(a_row + t*16) * PROWB
                            + (unsigned)(ks*16 + a_c8) * 2;
                ldm_x4(ahi + t*4, sA  + ar);
                ldm_x4(alo + t*4, sAl + ar);
            }
#pragma unroll
            for (int jp = 0; jp < 4; jp++) {
                unsigned br = (unsigned)(b_row + jp*16) * PROWB
                            + (unsigned)(ks*16 + b_c8) * 2;
                unsigned bhi[4], blo[4];
                ldm_x4(bhi, sBh + br);
                ldm_x4(blo, sBl + br);
#pragma unroll
                for (int tn = 0; tn < 2; tn++) {
#pragma unroll
                    for (int mi = 0; mi < 2; mi++) {
                        float* a4 = acc[mi][jp*2 + tn];
                        mma16816(a4, ahi + mi*4, bhi + tn*2);
                        mma16816(a4, ahi + mi*4, blo + tn*2);
                        mma16816(a4, alo + mi*4, bhi + tn*2);
                    }
                }
            }
        }
        __syncthreads();
    }

    const int g = lane >> 2, tig = lane & 3;
    __nv_bfloat16* Dh = (mode == 0) ? g_Qh : (mode == 1) ? g_Kh : g_Vh;
    __nv_bfloat16* Dl = (mode == 0) ? g_Ql : (mode == 1) ? g_Kl : g_Vl;
#pragma unroll
    for (int mi = 0; mi < 2; mi++) {
#pragma unroll
        for (int nj = 0; nj < 8; nj++) {
            int col = colBase + wn*64 + nj*8 + tig*2;
            float b0 = __ldg(&bias[col]);
            float b1 = __ldg(&bias[col+1]);
#pragma unroll
            for (int rh = 0; rh < 2; rh++) {
                int row = rowBase + wm*32 + mi*16 + g + rh*8;
                float v0 = acc[mi][nj][rh*2+0] + b0;
                float v1 = acc[mi][nj][rh*2+1] + b1;
                if (mode < 3) {
                    int b_ = row >> 11, s_ = row & (SS - 1);
                    int h_ = col >> 6,  d_ = col & 63;
                    size_t idx = (size_t)(((b_*HH) + h_)*SS + s_)*DHD + d_;
                    __nv_bfloat16 h0, l0, h1, l1;
                    split2(v0, h0, l0); split2(v1, h1, l1);
                    *(unsigned*)(Dh + idx) = pk(h0, h1);
                    *(unsigned*)(Dl + idx) = pk(l0, l1);
                } else {
                    float2 w2 = make_float2(v0, v1);
                    *(float2*)(out_ext + (size_t)row * DD + col) = w2;
                }
            }
        }
    }
}

// ---------------------------------------------------------------------------
// Pass 1 (HMMA): S = Q K^T * scale; t = exp(s - 8) -> attn (streaming stores);
// l = row sums.
// ---------------------------------------------------------------------------
#define KSTR 144
#define KPLANE (128*KSTR)                  // 18432
#define SK_OFF (2*KPLANE)
#define SRED (SK_OFF + 2*2*KPLANE)         // 110592
#define S1_SMEM (SRED + 128*2*4)           // 111616

__global__ __launch_bounds__(256) void scores_hmma(float* __restrict__ attn)
{
    extern __shared__ char sm[];
    const unsigned sb = s2u(sm);
    const int qt = (SS/128 - 1) - blockIdx.x;   // heavy CTAs first
    const int h = blockIdx.y, b = blockIdx.z;
    const int bh = b*HH + h;
    const int tid = threadIdx.x, wid = tid>>5, lane = tid&31;
    const int wm = wid>>1, wn = wid&1;
    const int g = lane>>2, tig = lane&3;
    const int qtb = qt*128;

    float* attn_bh = attn + (size_t)bh*SS*SS;
    float* redl = (float*)(sm + SRED);

    for (int i = tid; i < 2048; i += 256) {
        int pl = i >> 10, r = (i >> 3) & 127, sg = i & 7;
        const __nv_bfloat16* src =
            (pl ? g_Ql : g_Qh) + (size_t)(bh*SS + qtb + r)*DHD + sg*8;
        cpa16(sb + (unsigned)pl*KPLANE + (unsigned)r*KSTR + sg*16, src);
    }
    auto ISSUEK = [&](int kt) {
        const unsigned st = sb + SK_OFF + (unsigned)(kt & 1) * (2*KPLANE);
        const int ktb = kt*128;
        for (int i = tid; i < 2048; i += 256) {
            int pl = i >> 10, r = (i >> 3) & 127, sg = i & 7;
            const __nv_bfloat16* src =
                (pl ? g_Kl : g_Kh) + (size_t)(bh*SS + ktb + r)*DHD + sg*8;
            cpa16(st + (unsigned)pl*KPLANE + (unsigned)r*KSTR + sg*16, src);
        }
    };
    ISSUEK(0); CP_COMMIT();

    float rsum[4] = {0.f, 0.f, 0.f, 0.f};

    const int a_row = wm*32 + (lane&15);
    const int a_c8  = (lane>>4) << 3;
    const int b_row = wn*64 + (((lane>>4)&1)<<3) + (lane&7);
    const int b_c8  = ((lane>>3)&1) << 3;

    for (int kt = 0; kt <= qt; kt++) {
        if (kt < qt) { ISSUEK(kt + 1); CP_COMMIT(); CP_WAIT1(); }
        else         { CP_WAIT0(); }
        __syncthreads();

        const unsigned sKh = sb + SK_OFF + (unsigned)(kt & 1) * (2*KPLANE);
        const unsigned sKl = sKh + KPLANE;
        const int ktb = kt*128;

        float acc[2][8][4];
#pragma unroll
        for (int i = 0; i < 2; i++)
#pragma unroll
            for (int j = 0; j < 8; j++)
#pragma unroll
                for (int v = 0; v < 4; v++) acc[i][j][v] = 0.f;

#pragma unroll
        for (int ks = 0; ks < 4; ks++) {
            unsigned arow = (unsigned)a_row * KSTR + (unsigned)(ks*16 + a_c8)*2;
            unsigned ahi[2][4], alo[2][4];
            ldm_x4(ahi[0], sb + arow);
            ldm_x4(alo[0], sb + KPLANE + arow);
            ldm_x4(ahi[1], sb + arow + 16*KSTR);
            ldm_x4(alo[1], sb + KPLANE + arow + 16*KSTR);
#pragma unroll
            for (int jp = 0; jp < 4; jp++) {
                unsigned br = (unsigned)(b_row + jp*16)*KSTR
                            + (unsigned)(ks*16 + b_c8)*2;
                unsigned bhi[4], blo[4];
                ldm_x4(bhi, sKh + br);
                ldm_x4(blo, sKl + br);
#pragma unroll
                for (int tn = 0; tn < 2; tn++) {
#pragma unroll
                    for (int mi = 0; mi < 2; mi++) {
                        float* a4 = acc[mi][jp*2+tn];
                        mma16816(a4, ahi[mi], bhi + tn*2);
                        mma16816(a4, ahi[mi], blo + tn*2);
                        mma16816(a4, alo[mi], bhi + tn*2);
                    }
                }
            }
        }

        const bool diag = (kt == qt);
#pragma unroll
        for (int mi = 0; mi < 2; mi++) {
#pragma unroll
            for (int rh = 0; rh < 2; rh++) {
                int qgl = wm*32 + mi*16 + g + rh*8;
#pragma unroll
                for (int nj = 0; nj < 8; nj++) {
                    int kgl = wn*64 + nj*8 + tig*2;
                    float t0 = __expf(fmaf(acc[mi][nj][rh*2+0], ATTN_SCALE, -CSHIFT));
                    float t1 = __expf(fmaf(acc[mi][nj][rh*2+1], ATTN_SCALE, -CSHIFT));
                    if (diag) {
                        if (kgl   > qgl) t0 = 0.f;
                        if (kgl+1 > qgl) t1 = 0.f;
                    }
                    rsum[mi*2+rh] += t0 + t1;
                    __stcs((float2*)(attn_bh + (size_t)(qtb+qgl)*SS + ktb + kgl),
                           make_float2(t0, t1));
                }
            }
        }
        __syncthreads();
    }

#pragma unroll
    for (int i = 0; i < 4; i++) {
        rsum[i] += __shfl_xor_sync(0xffffffff, rsum[i], 1);
        rsum[i] += __shfl_xor_sync(0xffffffff, rsum[i], 2);
    }
    if (tig == 0) {
#pragma unroll
        for (int i = 0; i < 4; i++) {
            int rl = wm*32 + (i>>1)*16 + g + (i&1)*8;
            redl[rl*2 + wn] = rsum[i];
        }
    }
    __syncthreads();
    if (tid < 128)
        g_l[(size_t)bh*SS + qtb + tid] = redl[tid*2] + redl[tid*2+1];
}

// ---------------------------------------------------------------------------
// Pass 2 (HMMA): p = t/l (streaming ld/st), O = P V. 107 KB SMEM -> 2 CTA/SM.
// Single V buffer prefetched one tile ahead (load overlaps the convert phase
// of the same iteration). Zero-fill of the upper triangle issued first.
// ---------------------------------------------------------------------------
#define PSTR2 272
#define PPL2 (128*PSTR2)                   // 34816
#define AV_V (2*PPL2)                      // 69632: Vh, Vl (single stage)
#define AV_LI (AV_V + 2*KPLANE)            // 106496
#define S2_SMEM (AV_LI + 128*4)            // 107008

__global__ __launch_bounds__(256) void av_hmma(float* __restrict__ attn)
{
    extern __shared__ char sm[];
    const unsigned sb = s2u(sm);
    const int qt = (SS/128 - 1) - blockIdx.x;
    const int h = blockIdx.y, b = blockIdx.z;
    const int bh = b*HH + h;
    const int tid = threadIdx.x, wid = tid>>5, lane = tid&31;
    const int wm = wid>>1, wn = wid&1;
    const int g = lane>>2, tig = lane&3;
    const int qtb = qt*128;

    float* attn_bh = attn + (size_t)bh*SS*SS;
    float* li = (float*)(sm + AV_LI);

    if (tid < 128) li[tid] = 1.f / g_l[(size_t)bh*SS + qtb + tid];

    auto ISSUE_V = [&](int kt) {
        const int ktb = kt*128;
        for (int i = tid; i < 2048; i += 256) {
            int pl = i >> 10, r = (i >> 3) & 127, sg = i & 7;
            const __nv_bfloat16* src =
                (pl ? g_Vl : g_Vh) + (size_t)(bh*SS + ktb + r)*DHD + sg*8;
            cpa16(sb + AV_V + (unsigned)pl*KPLANE + (unsigned)r*KSTR + sg*16, src);
        }
    };
    ISSUE_V(0); CP_COMMIT();

    // zero-fill upper triangle (fire-and-forget streaming stores)
    {
        float4 z4 = make_float4(0.f, 0.f, 0.f, 0.f);
        for (int kt = qt + 1; kt < SS/128; kt++) {
            for (int v = tid; v < 4096; v += 256) {
                int r = v>>5, c4 = (v&31)<<2;
                __stcs((float4*)(attn_bh + (size_t)(qtb + r)*SS + kt*128 + c4), z4);
            }
        }
    }
    __syncthreads();                        // li visible to all

    float acc[2][4][4];
#pragma unroll
    for (int i = 0; i < 2; i++)
#pragma unroll
        for (int j = 0; j < 4; j++)
#pragma unroll
            for (int v = 0; v < 4; v++) acc[i][j][v] = 0.f;

    for (int kt = 0; kt <= qt; kt++) {
        const int ktb = kt*128;

        // convert: t (streaming LDG) -> p (streaming STG) + P planes (STS).
        // V(kt) cp.async (issued last iteration) overlaps this phase.
        for (int v = tid; v < 4096; v += 256) {
            int r = v>>5, c4 = (v&31)<<2;
            float* gp = attn_bh + (size_t)(qtb + r)*SS + ktb + c4;
            float4 t4 = __ldcs((const float4*)gp);
            float s = li[r];
            t4.x *= s; t4.y *= s; t4.z *= s; t4.w *= s;
            __stcs((float4*)gp, t4);
            __nv_bfloat16 hh[4], ll[4];
            split2(t4.x,hh[0],ll[0]); split2(t4.y,hh[1],ll[1]);
            split2(t4.z,hh[2],ll[2]); split2(t4.w,hh[3],ll[3]);
            unsigned so = (unsigned)r*PSTR2 + (unsigned)c4*2;
            *(uint2*)(sm + so)        = make_uint2(pk(hh[0],hh[1]), pk(hh[2],hh[3]));
            *(uint2*)(sm + PPL2 + so) = make_uint2(pk(ll[0],ll[1]), pk(ll[2],ll[3]));
        }
        CP_WAIT0();                          // V(kt) arrived
        __syncthreads();                     // P planes + V visible

        // O += P(128x128) @ V(128x64)
#pragma unroll
        for (int ks = 0; ks < 8; ks++) {
            unsigned arow = (unsigned)(wm*32 + (lane&15))*PSTR2
                          + (unsigned)(ks*16 + ((lane>>4)<<3))*2;
            unsigned ahi[2][4], alo[2][4];
            ldm_x4(ahi[0], sb + arow);
            ldm_x4(alo[0], sb + PPL2 + arow);
            ldm_x4(ahi[1], sb + arow + 16*PSTR2);
            ldm_x4(alo[1], sb + PPL2 + arow + 16*PSTR2);
#pragma unroll
            for (int jp = 0; jp < 2; jp++) {
                unsigned brow = (unsigned)(ks*16 + (((lane>>3)&1)<<3) + (lane&7))*KSTR
                              + (unsigned)(wn*32 + jp*16 + (((lane>>4)&1)<<3))*2;
                unsigned bhi[4], blo[4];
                ldm_x4_t(bhi, sb + AV_V + brow);
                ldm_x4_t(blo, sb + AV_V + KPLANE + brow);
#pragma unroll
                for (int tn = 0; tn < 2; tn++) {
#pragma unroll
                    for (int mi = 0; mi < 2; mi++) {
                        float* a4 = acc[mi][jp*2+tn];
                        mma16816(a4, ahi[mi], bhi + tn*2);
                        mma16816(a4, ahi[mi], blo + tn*2);
                        mma16816(a4, alo[mi], bhi + tn*2);
                    }
                }
            }
        }
        __syncthreads();                     // all warps done reading V/P
        if (kt < qt) { ISSUE_V(kt + 1); CP_COMMIT(); }
    }

    // write O planes (bf16 hi/lo) for the output projection
#pragma unroll
    for (int mi = 0; mi < 2; mi++) {
#pragma unroll
        for (int rh = 0; rh < 2; rh++) {
            int qg = qtb + wm*32 + mi*16 + g + rh*8;
            int n = b*SS + qg;
#pragma unroll
            for (int nj = 0; nj < 4; nj++) {
                int dd = h*DHD + wn*32 + nj*8 + tig*2;
                __nv_bfloat16 h0, l0, h1, l1;
                split2(acc[mi][nj][rh*2+0], h0, l0);
                split2(acc[mi][nj][rh*2+1], h1, l1);
                size_t idx = (size_t)n * DD + dd;
                *(unsigned*)(g_Oh + idx) = pk(h0, h1);
                *(unsigned*)(g_Ol + idx) = pk(l0, l1);
            }
        }
    }
}

// ---------------------------------------------------------------------------
extern "C" void kernel_launch(void* const* d_in, const int* in_sizes, int n_in,
                              void* d_out, int out_size)
{
    const float* qkv[3] = {nullptr, nullptr, nullptr};
    const float* Wm[4]  = {nullptr, nullptr, nullptr, nullptr};
    const float* bm[4]  = {nullptr, nullptr, nullptr, nullptr};
    int nq = 0, nw = 0, nb = 0;
    for (int i = 0; i < n_in; i++) {
        int sz = in_sizes[i];
        if (sz == NROWS*DD)      { if (nq < 3) qkv[nq++] = (const float*)d_in[i]; }
        else if (sz == DD*DD)    { if (nw < 4) Wm[nw++]  = (const float*)d_in[i]; }
        else if (sz == DD)       { if (nb < 4) bm[nb++]  = (const float*)d_in[i]; }
    }

    float* out  = (float*)d_out;
    float* attn = out + (size_t)NROWS * DD;

    static int smem_set = 0;
    if (!smem_set) {
        cudaFuncSetAttribute(proj_gemm_bf,
                             cudaFuncAttributeMaxDynamicSharedMemorySize, PROJ_SMEM);
        cudaFuncSetAttribute(scores_hmma,
                             cudaFuncAttributeMaxDynamicSharedMemorySize, S1_SMEM);
        cudaFuncSetAttribute(av_hmma,
                             cudaFuncAttributeMaxDynamicSharedMemorySize, S2_SMEM);
        smem_set = 1;
    }

    dim3 blk(256);
    prep_split<<<dim3(1024, 7), blk>>>(qkv[0], qkv[1], qkv[2],
                                       Wm[0], Wm[1], Wm[2], Wm[3]);

    dim3 ggrid(DD/128, NROWS/128);            // (8, 32)
    proj_gemm_bf<<<ggrid, blk, PROJ_SMEM>>>(bm[0], nullptr, 0);
    proj_gemm_bf<<<ggrid, blk, PROJ_SMEM>>>(bm[1], nullptr, 1);
    proj_gemm_bf<<<ggrid, blk, PROJ_SMEM>>>(bm[2], nullptr, 2);

    dim3 agrid(SS/128, HH, BB);               // (16, 16, 2)
    scores_hmma<<<agrid, blk, S1_SMEM>>>(attn);
    av_hmma<<<agrid, blk, S2_SMEM>>>(attn);

    proj_gemm_bf<<<ggrid, blk, PROJ_SMEM>>>(bm[3], out, 3);

    (void)out_size;
}

// round 13
// speedup vs baseline: 1.5475x; 1.1325x over previous
#include <cuda_runtime.h>
#include <cuda_bf16.h>
#include <math.h>

#define BB 2
#define SS 2048
#define DD 1024
#define HH 16
#define DHD 64
#define NROWS (BB*SS)        // 4096
#define NBH (BB*HH)          // 32
#define ATTN_SCALE 0.125f
#define CSHIFT 8.0f          // constant softmax shift (shift-invariant)

// ---------------------------------------------------------------------------
// Device-global scratch: bf16 hi/lo planes.
// ---------------------------------------------------------------------------
__device__ __nv_bfloat16 g_Xh[3][NROWS*DD];   // split query/key/value
__device__ __nv_bfloat16 g_Xl[3][NROWS*DD];
__device__ __nv_bfloat16 g_Wh[4][DD*DD];      // split Wq/Wk/Wv/Wo
__device__ __nv_bfloat16 g_Wl[4][DD*DD];
__device__ __nv_bfloat16 g_Qh[NBH*SS*DHD];    // [B,H,S,dh] planes
__device__ __nv_bfloat16 g_Ql[NBH*SS*DHD];
__device__ __nv_bfloat16 g_Kh[NBH*SS*DHD];
__device__ __nv_bfloat16 g_Kl[NBH*SS*DHD];
__device__ __nv_bfloat16 g_Vh[NBH*SS*DHD];
__device__ __nv_bfloat16 g_Vl[NBH*SS*DHD];
__device__ __nv_bfloat16 g_Oh[NROWS*DD];      // concat-heads planes
__device__ __nv_bfloat16 g_Ol[NROWS*DD];

// ===========================================================================
// helpers
// ===========================================================================
__device__ __forceinline__ unsigned s2u(const void* p) {
    unsigned a;
    asm("{ .reg .u64 t; cvta.to.shared.u64 t, %1; cvt.u32.u64 %0, t; }"
        : "=r"(a) : "l"(p));
    return a;
}
__device__ __forceinline__ void mma16816(float* c, const unsigned* a, const unsigned* b) {
    asm volatile(
        "mma.sync.aligned.m16n8k16.row.col.f32.bf16.bf16.f32 "
        "{%0,%1,%2,%3}, {%4,%5,%6,%7}, {%8,%9}, {%0,%1,%2,%3};"
        : "+f"(c[0]), "+f"(c[1]), "+f"(c[2]), "+f"(c[3])
        : "r"(a[0]), "r"(a[1]), "r"(a[2]), "r"(a[3]), "r"(b[0]), "r"(b[1]));
}
__device__ __forceinline__ void ldm_x4(unsigned* r, unsigned addr) {
    asm volatile("ldmatrix.sync.aligned.m8n8.x4.shared.b16 {%0,%1,%2,%3}, [%4];"
        : "=r"(r[0]), "=r"(r[1]), "=r"(r[2]), "=r"(r[3]) : "r"(addr));
}
__device__ __forceinline__ void ldm_x4_t(unsigned* r, unsigned addr) {
    asm volatile("ldmatrix.sync.aligned.m8n8.x4.trans.shared.b16 {%0,%1,%2,%3}, [%4];"
        : "=r"(r[0]), "=r"(r[1]), "=r"(r[2]), "=r"(r[3]) : "r"(addr));
}
__device__ __forceinline__ void split2(float x, __nv_bfloat16& h, __nv_bfloat16& l) {
    h = __float2bfloat16_rn(x);
    l = __float2bfloat16_rn(x - __bfloat162float(h));
}
__device__ __forceinline__ unsigned pk(__nv_bfloat16 a, __nv_bfloat16 b) {
    __nv_bfloat162 t(a, b);
    return *(unsigned*)&t;
}
__device__ __forceinline__ void cpa16(unsigned dst, const void* src) {
    asm volatile("cp.async.cg.shared.global [%0], [%1], 16;" :: "r"(dst), "l"(src));
}
#define CP_COMMIT() asm volatile("cp.async.commit_group;" ::: "memory")
#define CP_WAIT0()  asm volatile("cp.async.wait_group 0;" ::: "memory")
#define CP_WAIT1()  asm volatile("cp.async.wait_group 1;" ::: "memory")

// ---------------------------------------------------------------------------
// Prep: split inputs (q/k/v) and weights into bf16 hi/lo planes once.
// ---------------------------------------------------------------------------
__global__ __launch_bounds__(256) void prep_split(
    const float* __restrict__ q, const float* __restrict__ k,
    const float* __restrict__ v,
    const float* __restrict__ w0, const float* __restrict__ w1,
    const float* __restrict__ w2, const float* __restrict__ w3)
{
    const int z = blockIdx.y;
    const float* src;
    __nv_bfloat16 *dh, *dl;
    int n4;
    if (z < 3) {
        src = (z == 0) ? q : (z == 1) ? k : v;
        dh = g_Xh[z]; dl = g_Xl[z]; n4 = NROWS*DD/4;
    } else {
        int w = z - 3;
        src = (w == 0) ? w0 : (w == 1) ? w1 : (w == 2) ? w2 : w3;
        dh = g_Wh[w]; dl = g_Wl[w]; n4 = DD*DD/4;
    }
    for (int i = blockIdx.x * 256 + threadIdx.x; i < n4; i += gridDim.x * 256) {
        float4 x = ((const float4*)src)[i];
        __nv_bfloat16 h[4], l[4];
        split2(x.x, h[0], l[0]); split2(x.y, h[1], l[1]);
        split2(x.z, h[2], l[2]); split2(x.w, h[3], l[3]);
        ((uint2*)dh)[i] = make_uint2(pk(h[0], h[1]), pk(h[2], h[3]));
        ((uint2*)dl)[i] = make_uint2(pk(l[0], l[1]), pk(l[2], l[3]));
    }
}

// ---------------------------------------------------------------------------
// Projection GEMM (HMMA, bf16 planes, cp.async double-buffered).
// Sequential launches keep the ~41 MB working set L2-resident.
// mode 0/1/2 -> Q/K/V planes; 3 -> fp32 out.
// ---------------------------------------------------------------------------
#define PROWB 80
#define PPLANE 10240
#define PSTAGE (4*PPLANE)
#define PROJ_SMEM (2*PSTAGE)               // 81920

__global__ __launch_bounds__(256) void proj_gemm_bf(
    const float* __restrict__ bias, float* __restrict__ out_ext, int mode)
{
    extern __shared__ char smem[];
    const unsigned sb = s2u(smem);
    const int tid = threadIdx.x, wid = tid >> 5, lane = tid & 31;
    const int wm = wid >> 1, wn = wid & 1;
    const int rowBase = blockIdx.y * 128;
    const int colBase = blockIdx.x * 128;

    const __nv_bfloat16* Xh = (mode == 3) ? g_Oh : g_Xh[mode];
    const __nv_bfloat16* Xl = (mode == 3) ? g_Ol : g_Xl[mode];
    const __nv_bfloat16* Wh = g_Wh[mode];
    const __nv_bfloat16* Wl = g_Wl[mode];

    float acc[2][8][4];
#pragma unroll
    for (int i = 0; i < 2; i++)
#pragma unroll
        for (int j = 0; j < 8; j++)
#pragma unroll
            for (int v = 0; v < 4; v++) acc[i][j][v] = 0.f;

    auto ISSUE = [&](int c) {
        const int k0 = c * 32;
        const unsigned st = sb + (unsigned)(c & 1) * PSTAGE;
        for (int i = tid; i < 2048; i += 256) {
            int pl = i >> 9, r = (i >> 2) & 127, sg = i & 3;
            const __nv_bfloat16* srcp;
            if (pl == 0)      srcp = Xh + (size_t)(rowBase + r) * DD + k0 + sg*8;
            else if (pl == 1) srcp = Xl + (size_t)(rowBase + r) * DD + k0 + sg*8;
            else if (pl == 2) srcp = Wh + (size_t)(colBase + r) * DD + k0 + sg*8;
            else              srcp = Wl + (size_t)(colBase + r) * DD + k0 + sg*8;
            cpa16(st + (unsigned)pl * PPLANE + (unsigned)r * PROWB + sg*16, srcp);
        }
    };

    ISSUE(0); CP_COMMIT();

    const int a_row = wm*32 + (lane & 15);
    const int a_c8  = (lane >> 4) << 3;
    const int b_row = wn*64 + (((lane >> 4) & 1) << 3) + (lane & 7);
    const int b_c8  = ((lane >> 3) & 1) << 3;

    for (int c = 0; c < 32; c++) {
        if (c < 31) { ISSUE(c + 1); CP_COMMIT(); CP_WAIT1(); }
        else        { CP_WAIT0(); }
        __syncthreads();

        const unsigned sA  = sb + (unsigned)(c & 1) * PSTAGE;
        const unsigned sAl = sA + PPLANE;
        const unsigned sBh = sA + 2*PPLANE;
        const unsigned sBl = sA + 3*PPLANE;

#pragma unroll
        for (int ks = 0; ks < 2; ks++) {
            unsigned ahi[8], alo[8];
#pragma unroll
            for (int t = 0; t < 2; t++) {
                unsigned ar = (unsigned)(a_row + t*16) * PROWB
                            + (unsigned)(ks*16 + a_c8) * 2;
                ldm_x4(ahi + t*4, sA  + ar);
                ldm_x4(alo + t*4, sAl + ar);
            }
#pragma unroll
            for (int jp = 0; jp < 4; jp++) {
                unsigned br = (unsigned)(b_row + jp*16) * PROWB
                            + (unsigned)(ks*16 + b_c8) * 2;
                unsigned bhi[4], blo[4];
                ldm_x4(bhi, sBh + br);
                ldm_x4(blo, sBl + br);
#pragma unroll
                for (int tn = 0; tn < 2; tn++) {
#pragma unroll
                    for (int mi = 0; mi < 2; mi++) {
                        float* a4 = acc[mi][jp*2 + tn];
                        mma16816(a4, ahi + mi*4, bhi + tn*2);
                        mma16816(a4, ahi + mi*4, blo + tn*2);
                        mma16816(a4, alo + mi*4, bhi + tn*2);
                    }
                }
            }
        }
        __syncthreads();
    }

    const int g = lane >> 2, tig = lane & 3;
    __nv_bfloat16* Dh = (mode == 0) ? g_Qh : (mode == 1) ? g_Kh : g_Vh;
    __nv_bfloat16* Dl = (mode == 0) ? g_Ql : (mode == 1) ? g_Kl : g_Vl;
#pragma unroll
    for (int mi = 0; mi < 2; mi++) {
#pragma unroll
        for (int nj = 0; nj < 8; nj++) {
            int col = colBase + wn*64 + nj*8 + tig*2;
            float b0 = __ldg(&bias[col]);
            float b1 = __ldg(&bias[col+1]);
#pragma unroll
            for (int rh = 0; rh < 2; rh++) {
                int row = rowBase + wm*32 + mi*16 + g + rh*8;
                float v0 = acc[mi][nj][rh*2+0] + b0;
                float v1 = acc[mi][nj][rh*2+1] + b1;
                if (mode < 3) {
                    int b_ = row >> 11, s_ = row & (SS - 1);
                    int h_ = col >> 6,  d_ = col & 63;
                    size_t idx = (size_t)(((b_*HH) + h_)*SS + s_)*DHD + d_;
                    __nv_bfloat16 h0, l0, h1, l1;
                    split2(v0, h0, l0); split2(v1, h1, l1);
                    *(unsigned*)(Dh + idx) = pk(h0, h1);
                    *(unsigned*)(Dl + idx) = pk(l0, l1);
                } else {
                    float2 w2 = make_float2(v0, v1);
                    *(float2*)(out_ext + (size_t)row * DD + col) = w2;
                }
            }
        }
    }
}

// ---------------------------------------------------------------------------
// Fused attention (HMMA): pass A computes row sums l (QK + exp, no stores);
// pass B recomputes the bitwise-identical t, writes p = t/l directly (the
// only attn-matrix traffic), and accumulates O = P V.
// SMEM: Q | K (single; pass A also alternates into the V region) | V x2 | P.
// ---------------------------------------------------------------------------
#define KSTR 144
#define KPLANE (128*KSTR)                  // 18432
#define PSTR2 272
#define PPL2 (128*PSTR2)                   // 34816
#define FQ 0
#define FK (2*KPLANE)                      // 36864
#define FV (4*KPLANE)                      // 73728 (2 stages x 36864)
#define FP (8*KPLANE)                      // 147456 (Ph, Pl)
#define FRED (FP + 2*PPL2)                 // 217088
#define FLI (FRED + 1024)                  // 218112
#define S_FUSED (FLI + 512)                // 218624

__global__ __launch_bounds__(256) void attn_fused(float* __restrict__ attn)
{
    extern __shared__ char sm[];
    const unsigned sb = s2u(sm);
    const int qt = (SS/128 - 1) - blockIdx.x;   // heavy CTAs first
    const int h = blockIdx.y, b = blockIdx.z;
    const int bh = b*HH + h;
    const int tid = threadIdx.x, wid = tid>>5, lane = tid&31;
    const int wm = wid>>1, wn = wid&1;
    const int g = lane>>2, tig = lane&3;
    const int qtb = qt*128;

    float* attn_bh = attn + (size_t)bh*SS*SS;
    float* redl = (float*)(sm + FRED);
    float* li = (float*)(sm + FLI);

    // zero-fill upper triangle (fire-and-forget streaming stores)
    {
        float4 z4 = make_float4(0.f, 0.f, 0.f, 0.f);
        for (int kt = qt + 1; kt < SS/128; kt++)
            for (int v = tid; v < 4096; v += 256) {
                int r = v>>5, c4 = (v&31)<<2;
                __stcs((float4*)(attn_bh + (size_t)(qtb + r)*SS + kt*128 + c4), z4);
            }
    }

    // Q planes (bundled with first K group)
    for (int i = tid; i < 2048; i += 256) {
        int pl = i >> 10, r = (i >> 3) & 127, sg = i & 7;
        const __nv_bfloat16* src =
            (pl ? g_Ql : g_Qh) + (size_t)(bh*SS + qtb + r)*DHD + sg*8;
        cpa16(sb + FQ + (unsigned)pl*KPLANE + (unsigned)r*KSTR + sg*16, src);
    }
    auto ISSUE_K = [&](int kt, unsigned dstbase) {
        const int ktb = kt*128;
        for (int i = tid; i < 2048; i += 256) {
            int pl = i >> 10, r = (i >> 3) & 127, sg = i & 7;
            const __nv_bfloat16* src =
                (pl ? g_Kl : g_Kh) + (size_t)(bh*SS + ktb + r)*DHD + sg*8;
            cpa16(dstbase + (unsigned)pl*KPLANE + (unsigned)r*KSTR + sg*16, src);
        }
    };
    auto ISSUE_V = [&](int kt) {
        const unsigned st = sb + FV + (unsigned)(kt & 1) * (2*KPLANE);
        const int ktb = kt*128;
        for (int i = tid; i < 2048; i += 256) {
            int pl = i >> 10, r = (i >> 3) & 127, sg = i & 7;
            const __nv_bfloat16* src =
                (pl ? g_Vl : g_Vh) + (size_t)(bh*SS + ktb + r)*DHD + sg*8;
            cpa16(st + (unsigned)pl*KPLANE + (unsigned)r*KSTR + sg*16, src);
        }
    };

    const int a_row = wm*32 + (lane&15);
    const int a_c8  = (lane>>4) << 3;
    const int b_row = wn*64 + (((lane>>4)&1)<<3) + (lane&7);
    const int b_c8  = ((lane>>3)&1) << 3;

    // ======== pass A: row sums only ========
    ISSUE_K(0, sb + FK); CP_COMMIT();      // pass A alternates FK / FV regions
    float rsum[4] = {0.f, 0.f, 0.f, 0.f};

    for (int kt = 0; kt <= qt; kt++) {
        if (kt < qt) { ISSUE_K(kt + 1, sb + (((kt+1)&1) ? FV : FK));
                       CP_COMMIT(); CP_WAIT1(); }
        else         { CP_WAIT0(); }
        __syncthreads();

        const unsigned sKh = sb + ((kt&1) ? FV : FK);
        const unsigned sKl = sKh + KPLANE;

        float acc[2][8][4];
#pragma unroll
        for (int i = 0; i < 2; i++)
#pragma unroll
            for (int j = 0; j < 8; j++)
#pragma unroll
                for (int v = 0; v < 4; v++) acc[i][j][v] = 0.f;

#pragma unroll
        for (int ks = 0; ks < 4; ks++) {
            unsigned arow = (unsigned)a_row * KSTR + (unsigned)(ks*16 + a_c8)*2;
            unsigned ahi[2][4], alo[2][4];
            ldm_x4(ahi[0], sb + FQ + arow);
            ldm_x4(alo[0], sb + FQ + KPLANE + arow);
            ldm_x4(ahi[1], sb + FQ + arow + 16*KSTR);
            ldm_x4(alo[1], sb + FQ + KPLANE + arow + 16*KSTR);
#pragma unroll
            for (int jp = 0; jp < 4; jp++) {
                unsigned br = (unsigned)(b_row + jp*16)*KSTR
                            + (unsigned)(ks*16 + b_c8)*2;
                unsigned bhi[4], blo[4];
                ldm_x4(bhi, sKh + br);
                ldm_x4(blo, sKl + br);
#pragma unroll
                for (int tn = 0; tn < 2; tn++) {
#pragma unroll
                    for (int mi = 0; mi < 2; mi++) {
                        float* a4 = acc[mi][jp*2+tn];
                        mma16816(a4, ahi[mi], bhi + tn*2);
                        mma16816(a4, ahi[mi], blo + tn*2);
                        mma16816(a4, alo[mi], bhi + tn*2);
                    }
                }
            }
        }

        const bool diag = (kt == qt);
#pragma unroll
        for (int mi = 0; mi < 2; mi++) {
#pragma unroll
            for (int rh = 0; rh < 2; rh++) {
                int qgl = wm*32 + mi*16 + g + rh*8;
#pragma unroll
                for (int nj = 0; nj < 8; nj++) {
                    int kgl = wn*64 + nj*8 + tig*2;
                    float t0 = __expf(fmaf(acc[mi][nj][rh*2+0], ATTN_SCALE, -CSHIFT));
                    float t1 = __expf(fmaf(acc[mi][nj][rh*2+1], ATTN_SCALE, -CSHIFT));
                    if (diag) {
                        if (kgl   > qgl) t0 = 0.f;
                        if (kgl+1 > qgl) t1 = 0.f;
                    }
                    rsum[mi*2+rh] += t0 + t1;
                }
            }
        }
        __syncthreads();
    }

    // reduce rsum -> li (1/l) in SMEM
#pragma unroll
    for (int i = 0; i < 4; i++) {
        rsum[i] += __shfl_xor_sync(0xffffffff, rsum[i], 1);
        rsum[i] += __shfl_xor_sync(0xffffffff, rsum[i], 2);
    }
    if (tig == 0) {
#pragma unroll
        for (int i = 0; i < 4; i++) {
            int rl = wm*32 + (i>>1)*16 + g + (i&1)*8;
            redl[rl*2 + wn] = rsum[i];
        }
    }
    __syncthreads();
    if (tid < 128) li[tid] = 1.f / (redl[tid*2] + redl[tid*2+1]);
    __syncthreads();

    // ======== pass B: recompute t, write p, O += P V ========
    ISSUE_K(0, sb + FK); ISSUE_V(0); CP_COMMIT();

    float accO[2][4][4];
#pragma unroll
    for (int i = 0; i < 2; i++)
#pragma unroll
        for (int j = 0; j < 4; j++)
#pragma unroll
            for (int v = 0; v < 4; v++) accO[i][j][v] = 0.f;

    for (int kt = 0; kt <= qt; kt++) {
        const int ktb = kt*128;
        CP_WAIT0();
        __syncthreads();                   // K(kt), V(kt) ready

        float acc[2][8][4];
#pragma unroll
        for (int i = 0; i < 2; i++)
#pragma unroll
            for (int j = 0; j < 8; j++)
#pragma unroll
                for (int v = 0; v < 4; v++) acc[i][j][v] = 0.f;

#pragma unroll
        for (int ks = 0; ks < 4; ks++) {
            unsigned arow = (unsigned)a_row * KSTR + (unsigned)(ks*16 + a_c8)*2;
            unsigned ahi[2][4], alo[2][4];
            ldm_x4(ahi[0], sb + FQ + arow);
            ldm_x4(alo[0], sb + FQ + KPLANE + arow);
            ldm_x4(ahi[1], sb + FQ + arow + 16*KSTR);
            ldm_x4(alo[1], sb + FQ + KPLANE + arow + 16*KSTR);
#pragma unroll
            for (int jp = 0; jp < 4; jp++) {
                unsigned br = (unsigned)(b_row + jp*16)*KSTR
                            + (unsigned)(ks*16 + b_c8)*2;
                unsigned bhi[4], blo[4];
                ldm_x4(bhi, sb + FK + br);
                ldm_x4(blo, sb + FK + KPLANE + br);
#pragma unroll
                for (int tn = 0; tn < 2; tn++) {
#pragma unroll
                    for (int mi = 0; mi < 2; mi++) {
                        float* a4 = acc[mi][jp*2+tn];
                        mma16816(a4, ahi[mi], bhi + tn*2);
                        mma16816(a4, ahi[mi], blo + tn*2);
                        mma16816(a4, alo[mi], bhi + tn*2);
                    }
                }
            }
        }

        // epilogue: p = t * li[row]; write p (streaming) + P planes (STS)
        const bool diag = (kt == qt);
#pragma unroll
        for (int mi = 0; mi < 2; mi++) {
#pragma unroll
            for (int rh = 0; rh < 2; rh++) {
                int qgl = wm*32 + mi*16 + g + rh*8;
                float liv = li[qgl];
#pragma unroll
                for (int nj = 0; nj < 8; nj++) {
                    int kgl = wn*64 + nj*8 + tig*2;
                    float t0 = __expf(fmaf(acc[mi][nj][rh*2+0], ATTN_SCALE, -CSHIFT));
                    float t1 = __expf(fmaf(acc[mi][nj][rh*2+1], ATTN_SCALE, -CSHIFT));
                    if (diag) {
                        if (kgl   > qgl) t0 = 0.f;
                        if (kgl+1 > qgl) t1 = 0.f;
                    }
                    float p0 = t0 * liv, p1 = t1 * liv;
                    __stcs((float2*)(attn_bh + (size_t)(qtb+qgl)*SS + ktb + kgl),
                           make_float2(p0, p1));
                    __nv_bfloat16 h0, l0, h1, l1;
                    split2(p0, h0, l0); split2(p1, h1, l1);
                    unsigned so = (unsigned)qgl*PSTR2 + (unsigned)kgl*2;
                    *(unsigned*)(sm + FP + so)        = pk(h0, h1);
                    *(unsigned*)(sm + FP + PPL2 + so) = pk(l0, l1);
                }
            }
        }
        __syncthreads();                   // P planes visible; K consumed

        if (kt < qt) { ISSUE_K(kt + 1, sb + FK); ISSUE_V(kt + 1); CP_COMMIT(); }

        // O += P(128x128) @ V(128x64)   (overlaps next K/V loads)
        const unsigned sVh = sb + FV + (unsigned)(kt & 1) * (2*KPLANE);
        const unsigned sVl = sVh + KPLANE;
#pragma unroll
        for (int ks = 0; ks < 8; ks++) {
            unsigned arow = (unsigned)(wm*32 + (lane&15))*PSTR2
                          + (unsigned)(ks*16 + ((lane>>4)<<3))*2;
            unsigned ahi[2][4], alo[2][4];
            ldm_x4(ahi[0], sb + FP + arow);
            ldm_x4(alo[0], sb + FP + PPL2 + arow);
            ldm_x4(ahi[1], sb + FP + arow + 16*PSTR2);
            ldm_x4(alo[1], sb + FP + PPL2 + arow + 16*PSTR2);
#pragma unroll
            for (int jp = 0; jp < 2; jp++) {
                unsigned brow = (unsigned)(ks*16 + (((lane>>3)&1)<<3) + (lane&7))*KSTR
                              + (unsigned)(wn*32 + jp*16 + (((lane>>4)&1)<<3))*2;
                unsigned bhi[4], blo[4];
                ldm_x4_t(bhi, sVh + brow);
                ldm_x4_t(blo, sVl + brow);
#pragma unroll
                for (int tn = 0; tn < 2; tn++) {
#pragma unroll
                    for (int mi = 0; mi < 2; mi++) {
                        float* a4 = accO[mi][jp*2+tn];
                        mma16816(a4, ahi[mi], bhi + tn*2);
                        mma16816(a4, ahi[mi], blo + tn*2);
                        mma16816(a4, alo[mi], bhi + tn*2);
                    }
                }
            }
        }
    }

    // write O planes (bf16 hi/lo) for the output projection
#pragma unroll
    for (int mi = 0; mi < 2; mi++) {
#pragma unroll
        for (int rh = 0; rh < 2; rh++) {
            int qg = qtb + wm*32 + mi*16 + g + rh*8;
            int n = b*SS + qg;
#pragma unroll
            for (int nj = 0; nj < 4; nj++) {
                int dd = h*DHD + wn*32 + nj*8 + tig*2;
                __nv_bfloat16 h0, l0, h1, l1;
                split2(accO[mi][nj][rh*2+0], h0, l0);
                split2(accO[mi][nj][rh*2+1], h1, l1);
                size_t idx = (size_t)n * DD + dd;
                *(unsigned*)(g_Oh + idx) = pk(h0, h1);
                *(unsigned*)(g_Ol + idx) = pk(l0, l1);
            }
        }
    }
}

// ---------------------------------------------------------------------------
extern "C" void kernel_launch(void* const* d_in, const int* in_sizes, int n_in,
                              void* d_out, int out_size)
{
    const float* qkv[3] = {nullptr, nullptr, nullptr};
    const float* Wm[4]  = {nullptr, nullptr, nullptr, nullptr};
    const float* bm[4]  = {nullptr, nullptr, nullptr, nullptr};
    int nq = 0, nw = 0, nb = 0;
    for (int i = 0; i < n_in; i++) {
        int sz = in_sizes[i];
        if (sz == NROWS*DD)      { if (nq < 3) qkv[nq++] = (const float*)d_in[i]; }
        else if (sz == DD*DD)    { if (nw < 4) Wm[nw++]  = (const float*)d_in[i]; }
        else if (sz == DD)       { if (nb < 4) bm[nb++]  = (const float*)d_in[i]; }
    }

    float* out  = (float*)d_out;
    float* attn = out + (size_t)NROWS * DD;

    static int smem_set = 0;
    if (!smem_set) {
        cudaFuncSetAttribute(proj_gemm_bf,
                             cudaFuncAttributeMaxDynamicSharedMemorySize, PROJ_SMEM);
        cudaFuncSetAttribute(attn_fused,
                             cudaFuncAttributeMaxDynamicSharedMemorySize, S_FUSED);
        smem_set = 1;
    }

    dim3 blk(256);
    prep_split<<<dim3(1024, 7), blk>>>(qkv[0], qkv[1], qkv[2],
                                       Wm[0], Wm[1], Wm[2], Wm[3]);

    dim3 ggrid(DD/128, NROWS/128);            // (8, 32)
    proj_gemm_bf<<<ggrid, blk, PROJ_SMEM>>>(bm[0], nullptr, 0);
    proj_gemm_bf<<<ggrid, blk, PROJ_SMEM>>>(bm[1], nullptr, 1);
    proj_gemm_bf<<<ggrid, blk, PROJ_SMEM>>>(bm[2], nullptr, 2);

    dim3 agrid(SS/128, HH, BB);               // (16, 16, 2)
    attn_fused<<<agrid, blk, S_FUSED>>>(attn);

    proj_gemm_bf<<<ggrid, blk, PROJ_SMEM>>>(bm[3], out, 3);

    (void)out_size;
}